// round 13
// baseline (speedup 1.0000x reference)
#include <cuda_runtime.h>

#define NG    16
#define WARPS 8
#define TPB   (WARPS * 32)

// 64 * log(2*pi)
#define D_LOG_2PI 117.6241322f

// Volatile 128-bit load: keeps all burst loads in program order at the top of
// the kernel so ptxas cannot sink them into the MUFU-heavy compute loop.
#define LDG4(dst, ptr)                                                        \
    asm volatile("ld.global.nc.v4.f32 {%0,%1,%2,%3}, [%4];"                   \
                 : "=f"((dst).x), "=f"((dst).y), "=f"((dst).z), "=f"((dst).w) \
                 : "l"(ptr))

__global__ void __launch_bounds__(TPB) gmm_loss_kernel(
    const float4* __restrict__ means,
    const float4* __restrict__ covs,
    const float*  __restrict__ weights,
    const float4* __restrict__ targets,
    float* __restrict__ out)
{
    const int warp = threadIdx.x >> 5;
    const int lane = threadIdx.x & 31;
    const int b    = blockIdx.x * WARPS + warp;

    const int s    = lane & 15;   // sub-lane within 16-lane half
    const int half = lane >> 4;   // 0: even gaussians, 1: odd gaussians

    // Row base in units of float4: each row is 16*64 floats = 256 float4s.
    const size_t row4 = (size_t)b * 256;

    // ---- Load burst: 16x LDG.128 issued back-to-back (volatile ordering) ----
    float4 t4;
    LDG4(t4, targets + (size_t)b * 16 + s);

    float4 mu[8], vv[8];
    #pragma unroll
    for (int c = 0; c < 8; c++) {
        const size_t idx = row4 + c * 32 + lane;
        LDG4(mu[c], means + idx);
        LDG4(vv[c], covs  + idx);
    }

    // This lane's final gaussian after folding: value v = 4*b1 + 2*b2 + b3.
    const int vidx = ((s >> 1) & 1) * 4 + ((s >> 2) & 1) * 2 + ((s >> 3) & 1);
    const int g    = 2 * vidx + half;
    const float wt = __ldg(weights + (size_t)b * NG + g);  // overlaps with compute

    // Per-chunk fused partial: h[c] = sum(e^2/v) + sum(log v) over this lane's 4 dims.
    // Common-denominator form: ONE divide + ONE log per chunk.
    float h[8];
    #pragma unroll
    for (int c = 0; c < 8; c++) {
        const float4 m4 = mu[c];
        const float4 v4 = vv[c];
        const float e0 = t4.x - m4.x;
        const float e1 = t4.y - m4.y;
        const float e2 = t4.z - m4.z;
        const float e3 = t4.w - m4.w;
        const float p01 = v4.x * v4.y;
        const float p23 = v4.z * v4.w;
        const float P   = p01 * p23;           // product of 4 variances
        float num = (e0 * e0) * (v4.y * p23);
        num = fmaf(e1 * e1, v4.x * p23, num);
        num = fmaf(e2 * e2, v4.w * p01, num);
        num = fmaf(e3 * e3, v4.z * p01, num);
        h[c] = __fdividef(num, P) + __logf(P); // quad partial + logdet partial
    }

    // ---- Value-lane folding: 8 values over 16 lanes, single quantity ----
    const bool b3 = (s & 8) != 0;
    const bool b2 = (s & 4) != 0;
    const bool b1 = (s & 2) != 0;

    // Stage A (off=8): 8 -> 4 values. value(a_k) = 2k + b3
    float a[4];
    #pragma unroll
    for (int k = 0; k < 4; k++) {
        float kv = b3 ? h[2*k+1] : h[2*k];
        float sv = b3 ? h[2*k]   : h[2*k+1];
        a[k] = kv + __shfl_xor_sync(0xffffffffu, sv, 8);
    }

    // Stage B (off=4): 4 -> 2. value(u_j) = 4j + 2*b2 + b3
    float u[2];
    #pragma unroll
    for (int j = 0; j < 2; j++) {
        float kv = b2 ? a[2*j+1] : a[2*j];
        float sv = b2 ? a[2*j]   : a[2*j+1];
        u[j] = kv + __shfl_xor_sync(0xffffffffu, sv, 4);
    }

    // Stage C (off=2): 2 -> 1. value = 4*b1 + 2*b2 + b3 = vidx
    float kv = b1 ? u[1] : u[0];
    float sv = b1 ? u[0] : u[1];
    float w  = kv + __shfl_xor_sync(0xffffffffu, sv, 2);

    // Stage D (off=1): complete the 16-lane sum (lanes s and s^1 duplicate).
    w += __shfl_xor_sync(0xffffffffu, w, 1);

    // ---- Epilogue: all 32 lanes finish their gaussian in parallel ----
    float lp = -0.5f * (D_LOG_2PI + w);        // w = logdet + quad
    lp = fminf(fmaxf(lp, -100.0f), 0.0f);
    lp += __logf(wt);

    // logsumexp over offsets {2,4,8,16}: bit0 is the duplicate axis, so each
    // of the 16 gaussians is counted exactly once.
    float m = lp;
    m = fmaxf(m, __shfl_xor_sync(0xffffffffu, m, 2));
    m = fmaxf(m, __shfl_xor_sync(0xffffffffu, m, 4));
    m = fmaxf(m, __shfl_xor_sync(0xffffffffu, m, 8));
    m = fmaxf(m, __shfl_xor_sync(0xffffffffu, m, 16));

    float e = __expf(lp - m);
    e += __shfl_xor_sync(0xffffffffu, e, 2);
    e += __shfl_xor_sync(0xffffffffu, e, 4);
    e += __shfl_xor_sync(0xffffffffu, e, 8);
    e += __shfl_xor_sync(0xffffffffu, e, 16);

    if (lane == 0)
        out[b] = -(m + __logf(e));
}

extern "C" void kernel_launch(void* const* d_in, const int* in_sizes, int n_in,
                              void* d_out, int out_size)
{
    const float4* means   = (const float4*)d_in[0];
    const float4* covs    = (const float4*)d_in[1];
    const float*  weights = (const float*)d_in[2];
    const float4* targets = (const float4*)d_in[3];
    float*        out     = (float*)d_out;

    const int B = in_sizes[2] / NG;   // weights has B*16 elements

    gmm_loss_kernel<<<B / WARPS, TPB>>>(means, covs, weights, targets, out);
}

// round 14
// speedup vs baseline: 1.0274x; 1.0274x over previous
#include <cuda_runtime.h>

#define NG    16
#define WARPS 8
#define TPB   (WARPS * 32)

// 64 * log(2*pi)
#define D_LOG_2PI 117.6241322f

// Volatile 128-bit load: ordered relative to other volatile asm statements.
#define LDG4(dst, ptr)                                                        \
    asm volatile("ld.global.nc.v4.f32 {%0,%1,%2,%3}, [%4];"                   \
                 : "=f"((dst).x), "=f"((dst).y), "=f"((dst).z), "=f"((dst).w) \
                 : "l"(ptr))

// Empty volatile asm requiring a chunk's values: forces all preceding volatile
// loads to be issued first AND all their destinations to be live here, so
// ptxas cannot sink loads into the compute loop to save registers.
#define KEEP8(a, b)                                                           \
    asm volatile("" :: "f"((a).x), "f"((a).y), "f"((a).z), "f"((a).w),        \
                       "f"((b).x), "f"((b).y), "f"((b).z), "f"((b).w))

__global__ void __launch_bounds__(TPB) gmm_loss_kernel(
    const float4* __restrict__ means,
    const float4* __restrict__ covs,
    const float*  __restrict__ weights,
    const float4* __restrict__ targets,
    float* __restrict__ out)
{
    const int warp = threadIdx.x >> 5;
    const int lane = threadIdx.x & 31;
    const int b    = blockIdx.x * WARPS + warp;

    const int s    = lane & 15;   // sub-lane within 16-lane half
    const int half = lane >> 4;   // 0: even gaussians, 1: odd gaussians

    // Row base in units of float4: each row is 16*64 floats = 256 float4s.
    const size_t row4 = (size_t)b * 256;

    // ---- Load burst: 16x LDG.128 issued back-to-back ----
    float4 t4;
    LDG4(t4, targets + (size_t)b * 16 + s);

    float4 mu[8], vv[8];
    #pragma unroll
    for (int c = 0; c < 8; c++) {
        const size_t idx = row4 + c * 32 + lane;
        LDG4(mu[c], means + idx);
        LDG4(vv[c], covs  + idx);
    }

    // Barrier: all 16 loads must be issued before this point, and all 64
    // destination registers are simultaneously live here.
    #pragma unroll
    for (int c = 0; c < 8; c++)
        KEEP8(mu[c], vv[c]);

    // This lane's final gaussian after folding: value v = 4*b1 + 2*b2 + b3.
    const int vidx = ((s >> 1) & 1) * 4 + ((s >> 2) & 1) * 2 + ((s >> 3) & 1);
    const int g    = 2 * vidx + half;
    const float wt = __ldg(weights + (size_t)b * NG + g);  // overlaps with compute

    // Per-chunk fused partial: h[c] = sum(e^2/v) + sum(log v) over this lane's 4 dims.
    // Common-denominator form: ONE divide + ONE log per chunk.
    float h[8];
    #pragma unroll
    for (int c = 0; c < 8; c++) {
        const float4 m4 = mu[c];
        const float4 v4 = vv[c];
        const float e0 = t4.x - m4.x;
        const float e1 = t4.y - m4.y;
        const float e2 = t4.z - m4.z;
        const float e3 = t4.w - m4.w;
        const float p01 = v4.x * v4.y;
        const float p23 = v4.z * v4.w;
        const float P   = p01 * p23;           // product of 4 variances
        float num = (e0 * e0) * (v4.y * p23);
        num = fmaf(e1 * e1, v4.x * p23, num);
        num = fmaf(e2 * e2, v4.w * p01, num);
        num = fmaf(e3 * e3, v4.z * p01, num);
        h[c] = __fdividef(num, P) + __logf(P); // quad partial + logdet partial
    }

    // ---- Value-lane folding: 8 values over 16 lanes, single quantity ----
    const bool b3 = (s & 8) != 0;
    const bool b2 = (s & 4) != 0;
    const bool b1 = (s & 2) != 0;

    // Stage A (off=8): 8 -> 4 values. value(a_k) = 2k + b3
    float a[4];
    #pragma unroll
    for (int k = 0; k < 4; k++) {
        float kv = b3 ? h[2*k+1] : h[2*k];
        float sv = b3 ? h[2*k]   : h[2*k+1];
        a[k] = kv + __shfl_xor_sync(0xffffffffu, sv, 8);
    }

    // Stage B (off=4): 4 -> 2. value(u_j) = 4j + 2*b2 + b3
    float u[2];
    #pragma unroll
    for (int j = 0; j < 2; j++) {
        float kv = b2 ? a[2*j+1] : a[2*j];
        float sv = b2 ? a[2*j]   : a[2*j+1];
        u[j] = kv + __shfl_xor_sync(0xffffffffu, sv, 4);
    }

    // Stage C (off=2): 2 -> 1. value = 4*b1 + 2*b2 + b3 = vidx
    float kv = b1 ? u[1] : u[0];
    float sv = b1 ? u[0] : u[1];
    float w  = kv + __shfl_xor_sync(0xffffffffu, sv, 2);

    // Stage D (off=1): complete the 16-lane sum (lanes s and s^1 duplicate).
    w += __shfl_xor_sync(0xffffffffu, w, 1);

    // ---- Epilogue: all 32 lanes finish their gaussian in parallel ----
    float lp = -0.5f * (D_LOG_2PI + w);        // w = logdet + quad
    lp = fminf(fmaxf(lp, -100.0f), 0.0f);
    lp += __logf(wt);

    // logsumexp over offsets {2,4,8,16}: bit0 is the duplicate axis, so each
    // of the 16 gaussians is counted exactly once.
    float m = lp;
    m = fmaxf(m, __shfl_xor_sync(0xffffffffu, m, 2));
    m = fmaxf(m, __shfl_xor_sync(0xffffffffu, m, 4));
    m = fmaxf(m, __shfl_xor_sync(0xffffffffu, m, 8));
    m = fmaxf(m, __shfl_xor_sync(0xffffffffu, m, 16));

    float e = __expf(lp - m);
    e += __shfl_xor_sync(0xffffffffu, e, 2);
    e += __shfl_xor_sync(0xffffffffu, e, 4);
    e += __shfl_xor_sync(0xffffffffu, e, 8);
    e += __shfl_xor_sync(0xffffffffu, e, 16);

    if (lane == 0)
        out[b] = -(m + __logf(e));
}

extern "C" void kernel_launch(void* const* d_in, const int* in_sizes, int n_in,
                              void* d_out, int out_size)
{
    const float4* means   = (const float4*)d_in[0];
    const float4* covs    = (const float4*)d_in[1];
    const float*  weights = (const float*)d_in[2];
    const float4* targets = (const float4*)d_in[3];
    float*        out     = (float*)d_out;

    const int B = in_sizes[2] / NG;   // weights has B*16 elements

    gmm_loss_kernel<<<B / WARPS, TPB>>>(means, covs, weights, targets, out);
}

// round 15
// speedup vs baseline: 1.0309x; 1.0034x over previous
#include <cuda_runtime.h>

#define NG    16
#define WARPS 8
#define TPB   (WARPS * 32)

// 64 * log(2*pi)
#define D_LOG_2PI 117.6241322f

__global__ void __launch_bounds__(TPB) gmm_loss_kernel(
    const float4* __restrict__ means,
    const float4* __restrict__ covs,
    const float*  __restrict__ weights,
    const float4* __restrict__ targets,
    float* __restrict__ out)
{
    const int warp = threadIdx.x >> 5;
    const int lane = threadIdx.x & 31;
    const int b    = blockIdx.x * WARPS + warp;

    const int s    = lane & 15;   // sub-lane within 16-lane half
    const int half = lane >> 4;   // 0: even gaussians, 1: odd gaussians

    // Row base in units of float4: each row is 16*64 floats = 256 float4s.
    const size_t row4 = (size_t)b * 256;

    // Target float4 for this lane: element d = (lane*4) % 64, same for every chunk.
    const float4 t4 = targets[(size_t)b * 16 + s];

    // Stage all 16 float4 loads (8 chunks x {means, covs}) for max MLP.
    float4 mu[8], vv[8];
    #pragma unroll
    for (int c = 0; c < 8; c++) {
        const size_t idx = row4 + c * 32 + lane;
        mu[c] = means[idx];
        vv[c] = covs[idx];
    }

    // This lane's final gaussian after folding: value v = 4*b1 + 2*b2 + b3.
    const int vidx = ((s >> 1) & 1) * 4 + ((s >> 2) & 1) * 2 + ((s >> 3) & 1);
    const int g    = 2 * vidx + half;
    const float wt = __ldg(weights + (size_t)b * NG + g);  // overlap with folding

    // Per-chunk partial quad sums and variance products.
    // Common-denominator form: ONE divide per chunk instead of four RCPs.
    // Chunk c, lanes 0-15 -> gaussian 2c; lanes 16-31 -> gaussian 2c+1.
    float q[8], pv[8];
    #pragma unroll
    for (int c = 0; c < 8; c++) {
        const float4 m4 = mu[c];
        const float4 v4 = vv[c];
        const float e0 = t4.x - m4.x;
        const float e1 = t4.y - m4.y;
        const float e2 = t4.z - m4.z;
        const float e3 = t4.w - m4.w;
        const float p01 = v4.x * v4.y;
        const float p23 = v4.z * v4.w;
        const float P   = p01 * p23;           // product of 4 variances
        float num = (e0 * e0) * (v4.y * p23);
        num = fmaf(e1 * e1, v4.x * p23, num);
        num = fmaf(e2 * e2, v4.w * p01, num);
        num = fmaf(e3 * e3, v4.z * p01, num);
        q[c]  = __fdividef(num, P);
        pv[c] = P;
    }

    // ---- Value-lane folding: reduce 8 values over 16 lanes in 8 shuffles each ----
    const bool b3 = (s & 8) != 0;
    const bool b2 = (s & 4) != 0;
    const bool b1 = (s & 2) != 0;

    // Stage A (off=8): 8 -> 4 values. value(a_k) = 2k + b3
    float aq[4], ap[4];
    #pragma unroll
    for (int k = 0; k < 4; k++) {
        float kq = b3 ? q[2*k+1]  : q[2*k];
        float sq = b3 ? q[2*k]    : q[2*k+1];
        aq[k] = kq + __shfl_xor_sync(0xffffffffu, sq, 8);
        float kp = b3 ? pv[2*k+1] : pv[2*k];
        float sp = b3 ? pv[2*k]   : pv[2*k+1];
        ap[k] = kp * __shfl_xor_sync(0xffffffffu, sp, 8);
    }

    // Stage B (off=4): 4 -> 2. value(u_j) = 4j + 2*b2 + b3
    float uq[2], up[2];
    #pragma unroll
    for (int j = 0; j < 2; j++) {
        float kq = b2 ? aq[2*j+1] : aq[2*j];
        float sq = b2 ? aq[2*j]   : aq[2*j+1];
        uq[j] = kq + __shfl_xor_sync(0xffffffffu, sq, 4);
        float kp = b2 ? ap[2*j+1] : ap[2*j];
        float sp = b2 ? ap[2*j]   : ap[2*j+1];
        up[j] = kp * __shfl_xor_sync(0xffffffffu, sp, 4);
    }

    // Stage C (off=2): 2 -> 1. value = 4*b1 + 2*b2 + b3 = vidx
    float kq = b1 ? uq[1] : uq[0];
    float sq = b1 ? uq[0] : uq[1];
    float wq = kq + __shfl_xor_sync(0xffffffffu, sq, 2);
    float kp = b1 ? up[1] : up[0];
    float sp = b1 ? up[0] : up[1];
    float wp = kp * __shfl_xor_sync(0xffffffffu, sp, 2);

    // Stage D (off=1): complete the 16-lane sum (lanes s and s^1 now duplicate).
    wq += __shfl_xor_sync(0xffffffffu, wq, 1);
    wp *= __shfl_xor_sync(0xffffffffu, wp, 1);

    // ---- Epilogue: all 32 lanes finish their gaussian in parallel ----
    const float logdet = __logf(wp);                 // == sum(log var)
    float lp = -0.5f * (D_LOG_2PI + logdet + wq);
    lp = fminf(fmaxf(lp, -100.0f), 0.0f);
    lp += __logf(wt);

    // logsumexp over offsets {2,4,8,16}: bit0 is the duplicate axis, so each
    // of the 16 gaussians is counted exactly once.
    float m = lp;
    m = fmaxf(m, __shfl_xor_sync(0xffffffffu, m, 2));
    m = fmaxf(m, __shfl_xor_sync(0xffffffffu, m, 4));
    m = fmaxf(m, __shfl_xor_sync(0xffffffffu, m, 8));
    m = fmaxf(m, __shfl_xor_sync(0xffffffffu, m, 16));

    float e = __expf(lp - m);
    e += __shfl_xor_sync(0xffffffffu, e, 2);
    e += __shfl_xor_sync(0xffffffffu, e, 4);
    e += __shfl_xor_sync(0xffffffffu, e, 8);
    e += __shfl_xor_sync(0xffffffffu, e, 16);

    if (lane == 0)
        out[b] = -(m + __logf(e));
}

extern "C" void kernel_launch(void* const* d_in, const int* in_sizes, int n_in,
                              void* d_out, int out_size)
{
    const float4* means   = (const float4*)d_in[0];
    const float4* covs    = (const float4*)d_in[1];
    const float*  weights = (const float*)d_in[2];
    const float4* targets = (const float4*)d_in[3];
    float*        out     = (float*)d_out;

    const int B = in_sizes[2] / NG;   // weights has B*16 elements

    gmm_loss_kernel<<<B / WARPS, TPB>>>(means, covs, weights, targets, out);
}